// round 6
// baseline (speedup 1.0000x reference)
#include <cuda_runtime.h>
#include <cuda_bf16.h>
#include <cstdint>

// ---------------------------------------------------------------------------
// Swin shifted-window attention, B=32 H=W=56 C=512 NH=16 HD=32 WS=7 SS=3
// fp32 SIMT pipeline:
//   k0: build row-index table (shift + window partition bijection)
//   k1: QKV GEMM  (gather-A)    X[100352,512] @ Wqkv^T[512,1536] + b -> g_qkv
//   k2: attention per (window, head)                              -> g_att
//   k3: proj GEMM (A = g_att global, scatter-C) @ Wp^T + b        -> out
//
// FIX vs previous round: the proj GEMM was receiving the HOST shadow address
// of the __device__ global g_att (passed as a kernel argument from host
// code). On GB300, ATS made that a silent read of zero host memory instead
// of a fault. The PROJ path now references g_att directly inside the kernel.
// ---------------------------------------------------------------------------

#define BATCH   32
#define IMG     56
#define CCH     512
#define NHEAD   16
#define HD      32
#define WS      7
#define SS      3
#define NTOK    49            // WS*WS
#define NWH     8             // IMG/WS
#define NWIN    64            // per image
#define TOTWIN  2048          // BATCH*NWIN
#define MROWS   100352        // TOTWIN*NTOK
#define QKVC    1536

// scratch (device globals: allocation-free)
__device__ float g_qkv[(size_t)MROWS * QKVC];   // 617 MB
__device__ float g_att[(size_t)MROWS * CCH];    // 205 MB
__device__ int   g_rowidx[MROWS];

// ---------------------------------------------------------------------------
__global__ void build_rowidx_kernel() {
    int m = blockIdx.x * 256 + threadIdx.x;
    if (m >= MROWS) return;
    int win = m / NTOK, n = m % NTOK;
    int b  = win >> 6, wi = win & 63;
    int wh = wi >> 3,  ww = wi & 7;
    int r = wh * WS + n / WS;
    int c = ww * WS + n % WS;
    int sh = r + SS; if (sh >= IMG) sh -= IMG;
    int sw = c + SS; if (sw >= IMG) sw -= IMG;
    g_rowidx[m] = (b * IMG + sh) * IMG + sw;
}

// ---------------------------------------------------------------------------
// Tiled fp32 GEMM: C[M,N] = A[M,512] * W[N,512]^T + bias[N]
// BM=BN=128, BK=8, 256 threads, 8x8 per-thread tile, double-buffered smem.
// QKV mode: A = x (param), rows gathered via g_rowidx, C -> g_qkv (ld 1536).
// PROJ mode: A = g_att (device global, addressed IN-KERNEL),
//            C scattered through g_rowidx into out.
// ---------------------------------------------------------------------------
template <bool QKV>
__global__ __launch_bounds__(256, 2)
void gemm_kernel(const float* __restrict__ Ain,
                 const float* __restrict__ W,
                 const float* __restrict__ bias,
                 float* __restrict__ out)
{
    __shared__ float As[2][8][128];
    __shared__ float Bs[2][8][128];

    const int tid = threadIdx.x;
    const int bm = blockIdx.y, bn = blockIdx.x;

    // loader mapping: 256 threads load 128x8 tile as float4
    const int lr = tid >> 1;            // 0..127
    const int lc = (tid & 1) * 4;       // 0 or 4
    const int gm = bm * 128 + lr;

    // Resolve A pointer INSIDE the kernel (device-global address is only
    // valid in device code).
    const float* A = QKV ? Ain : (const float*)g_att;
    size_t arow = QKV ? (size_t)g_rowidx[gm] * CCH : (size_t)gm * CCH;
    const float* aptr = A + arow + lc;
    const float* bptr = W + (size_t)(bn * 128 + lr) * CCH + lc;

    const int ty = tid >> 4, tx = tid & 15;

    float acc[8][8];
#pragma unroll
    for (int i = 0; i < 8; i++)
#pragma unroll
        for (int j = 0; j < 8; j++) acc[i][j] = 0.f;

    // prologue: tile 0
    float4 a4 = *(const float4*)aptr;
    float4 b4 = *(const float4*)bptr;
    As[0][lc + 0][lr] = a4.x; As[0][lc + 1][lr] = a4.y;
    As[0][lc + 2][lr] = a4.z; As[0][lc + 3][lr] = a4.w;
    Bs[0][lc + 0][lr] = b4.x; Bs[0][lc + 1][lr] = b4.y;
    Bs[0][lc + 2][lr] = b4.z; Bs[0][lc + 3][lr] = b4.w;
    __syncthreads();

    int buf = 0;
    const int KTILES = CCH / 8;    // 64
    for (int kt = 0; kt < KTILES; kt++) {
        float4 na, nb;
        if (kt + 1 < KTILES) {
            na = *(const float4*)(aptr + (kt + 1) * 8);
            nb = *(const float4*)(bptr + (kt + 1) * 8);
        }
#pragma unroll
        for (int k = 0; k < 8; k++) {
            float a[8], b[8];
            *(float4*)(a)     = *(const float4*)&As[buf][k][ty * 8];
            *(float4*)(a + 4) = *(const float4*)&As[buf][k][ty * 8 + 4];
            *(float4*)(b)     = *(const float4*)&Bs[buf][k][tx * 8];
            *(float4*)(b + 4) = *(const float4*)&Bs[buf][k][tx * 8 + 4];
#pragma unroll
            for (int i = 0; i < 8; i++)
#pragma unroll
                for (int j = 0; j < 8; j++)
                    acc[i][j] = fmaf(a[i], b[j], acc[i][j]);
        }
        if (kt + 1 < KTILES) {
            int nbuf = buf ^ 1;
            As[nbuf][lc + 0][lr] = na.x; As[nbuf][lc + 1][lr] = na.y;
            As[nbuf][lc + 2][lr] = na.z; As[nbuf][lc + 3][lr] = na.w;
            Bs[nbuf][lc + 0][lr] = nb.x; Bs[nbuf][lc + 1][lr] = nb.y;
            Bs[nbuf][lc + 2][lr] = nb.z; Bs[nbuf][lc + 3][lr] = nb.w;
            __syncthreads();
            buf = nbuf;
        }
    }

    // epilogue
    const int col = bn * 128 + tx * 8;
    float4 bs0 = *(const float4*)(bias + col);
    float4 bs1 = *(const float4*)(bias + col + 4);
#pragma unroll
    for (int i = 0; i < 8; i++) {
        int m = bm * 128 + ty * 8 + i;
        float* cp;
        if (QKV) cp = g_qkv + (size_t)m * QKVC + col;
        else     cp = out   + (size_t)g_rowidx[m] * CCH + col;
        float4 r0, r1;
        r0.x = acc[i][0] + bs0.x; r0.y = acc[i][1] + bs0.y;
        r0.z = acc[i][2] + bs0.z; r0.w = acc[i][3] + bs0.w;
        r1.x = acc[i][4] + bs1.x; r1.y = acc[i][5] + bs1.y;
        r1.z = acc[i][6] + bs1.z; r1.w = acc[i][7] + bs1.w;
        *(float4*)(cp)     = r0;
        *(float4*)(cp + 4) = r1;
    }
}

// ---------------------------------------------------------------------------
// Attention: one block per (window, head). 256 threads.
// q/k/v in smem (row stride 33 -> conflict-free column access), scores 49x49,
// rel-pos bias from per-head smem-cached table, analytic shift mask, softmax,
// P@V, write g_att[(win*49+n)*512 + h*32 + d].
// ---------------------------------------------------------------------------
#define QKS 33   // smem row stride for q/k/v

__global__ __launch_bounds__(256)
void attn_kernel(const float* __restrict__ rel)
{
    const int win = blockIdx.x >> 4;
    const int h   = blockIdx.x & 15;
    const int tid = threadIdx.x;

    __shared__ float qs[NTOK * QKS];
    __shared__ float ks[NTOK * QKS];
    __shared__ float vs[NTOK * QKS];
    __shared__ float S[NTOK][50];
    __shared__ float tb[169];
    __shared__ int   lab[NTOK];

    const float scale = 0.17677669529663687f;   // 32^-0.5
    const size_t base = (size_t)win * NTOK * QKVC + h * HD;

    // load q (scaled), k, v : 49 rows x 8 float4 each
    for (int e = tid; e < NTOK * 8; e += 256) {
        int n = e >> 3, c4 = (e & 7) * 4;
        const float* p = g_qkv + base + (size_t)n * QKVC + c4;
        float4 q4 = *(const float4*)(p);
        float4 k4 = *(const float4*)(p + 512);
        float4 v4 = *(const float4*)(p + 1024);
        float* qd = &qs[n * QKS + c4];
        float* kd = &ks[n * QKS + c4];
        float* vd = &vs[n * QKS + c4];
        qd[0] = q4.x * scale; qd[1] = q4.y * scale;
        qd[2] = q4.z * scale; qd[3] = q4.w * scale;
        kd[0] = k4.x; kd[1] = k4.y; kd[2] = k4.z; kd[3] = k4.w;
        vd[0] = v4.x; vd[1] = v4.y; vd[2] = v4.z; vd[3] = v4.w;
    }
    if (tid < 169) tb[tid] = rel[tid * NHEAD + h];
    if (tid < NTOK) {
        int wi = win & 63;
        int r = (wi >> 3) * WS + tid / WS;
        int c = (wi & 7) * WS + tid % WS;
        int rh = (r < IMG - WS) ? 0 : (r < IMG - SS ? 1 : 2);
        int rw = (c < IMG - WS) ? 0 : (c < IMG - SS ? 1 : 2);
        lab[tid] = rh * 3 + rw;
    }
    __syncthreads();

    // scores + bias + mask
    for (int e = tid; e < NTOK * NTOK; e += 256) {
        int n = e / NTOK, mm = e - n * NTOK;
        const float* qp = &qs[n * QKS];
        const float* kp = &ks[mm * QKS];
        float a = 0.f;
#pragma unroll
        for (int d = 0; d < HD; d++) a = fmaf(qp[d], kp[d], a);
        int dr = n / WS - mm / WS + (WS - 1);
        int dc = n % WS - mm % WS + (WS - 1);
        a += tb[dr * (2 * WS - 1) + dc];
        if (lab[n] != lab[mm]) a -= 100.0f;
        S[n][mm] = a;
    }
    __syncthreads();

    // row softmax: warp per row (strided)
    const int warp = tid >> 5, lane = tid & 31;
    for (int n = warp; n < NTOK; n += 8) {
        float v0 = (lane < NTOK)      ? S[n][lane]      : -1e30f;
        float v1 = (lane + 32 < NTOK) ? S[n][lane + 32] : -1e30f;
        float mx = fmaxf(v0, v1);
#pragma unroll
        for (int o = 16; o > 0; o >>= 1)
            mx = fmaxf(mx, __shfl_xor_sync(0xffffffffu, mx, o));
        float e0 = (lane < NTOK)      ? __expf(v0 - mx) : 0.f;
        float e1 = (lane + 32 < NTOK) ? __expf(v1 - mx) : 0.f;
        float sm = e0 + e1;
#pragma unroll
        for (int o = 16; o > 0; o >>= 1)
            sm += __shfl_xor_sync(0xffffffffu, sm, o);
        float inv = 1.0f / sm;
        if (lane < NTOK)      S[n][lane]      = e0 * inv;
        if (lane + 32 < NTOK) S[n][lane + 32] = e1 * inv;
    }
    __syncthreads();

    // out = P @ V  -> g_att
    const size_t obase = (size_t)win * NTOK * CCH + h * HD;
    for (int e = tid; e < NTOK * HD; e += 256) {
        int n = e >> 5, d = e & 31;
        float a = 0.f;
#pragma unroll
        for (int mm = 0; mm < NTOK; mm++)
            a = fmaf(S[n][mm], vs[mm * QKS + d], a);
        g_att[obase + (size_t)n * CCH + d] = a;
    }
}

// ---------------------------------------------------------------------------
extern "C" void kernel_launch(void* const* d_in, const int* in_sizes, int n_in,
                              void* d_out, int out_size)
{
    const float* x      = (const float*)d_in[0];
    const float* qkv_w  = (const float*)d_in[1];
    const float* qkv_b  = (const float*)d_in[2];
    const float* proj_w = (const float*)d_in[3];
    const float* proj_b = (const float*)d_in[4];
    const float* rel    = (const float*)d_in[5];
    float* out = (float*)d_out;

    build_rowidx_kernel<<<(MROWS + 255) / 256, 256>>>();

    // QKV: M=100352, N=1536, gather-A from x
    gemm_kernel<true><<<dim3(QKVC / 128, MROWS / 128), 256>>>(x, qkv_w, qkv_b, nullptr);

    // attention: (window, head) blocks
    attn_kernel<<<TOTWIN * NHEAD, 256>>>(rel);

    // proj: M=100352, N=512, A = g_att (resolved in-kernel), scatter to out
    gemm_kernel<false><<<dim3(CCH / 128, MROWS / 128), 256>>>(nullptr, proj_w, proj_b, out);
}

// round 8
// speedup vs baseline: 1.6852x; 1.6852x over previous
#include <cuda_runtime.h>
#include <cuda_bf16.h>
#include <cstdint>

// ---------------------------------------------------------------------------
// Swin shifted-window attention, B=32 H=W=56 C=512 NH=16 HD=32 WS=7 SS=3
//   k0: build row-index table
//   kw: convert weights fp32 -> bf16 hi/lo
//   k1: QKV GEMM  mma.sync bf16 3-term split (gather-A)  -> g_qkv
//   k2: attention per (window, head)                     -> g_att
//   k3: proj GEMM mma.sync bf16 3-term split (scatter-C) -> out
//
// tcgen05 is NOT available in this build (ptxas target is plain sm_103, no
// arch-specific 'a' features). mma.sync m16n8k16 bf16 + ldmatrix are sm_80+
// baseline and assemble fine. A*B ~= AhiBhi + AhiBlo + AloBhi, fp32 accum.
// ---------------------------------------------------------------------------

#define BATCH   32
#define IMG     56
#define CCH     512
#define NHEAD   16
#define HD      32
#define WS      7
#define SS      3
#define NTOK    49
#define TOTWIN  2048
#define MROWS   100352
#define QKVC    1536

// scratch (device globals: allocation-free; NEVER passed from host)
__device__ float g_qkv[(size_t)MROWS * QKVC];
__device__ float g_att[(size_t)MROWS * CCH];
__device__ int   g_rowidx[MROWS];
__device__ __nv_bfloat16 g_wqkv_hi[QKVC * CCH];
__device__ __nv_bfloat16 g_wqkv_lo[QKVC * CCH];
__device__ __nv_bfloat16 g_wp_hi[CCH * CCH];
__device__ __nv_bfloat16 g_wp_lo[CCH * CCH];

__device__ __forceinline__ uint32_t smem_u32(const void* p) {
    uint32_t a;
    asm("{ .reg .u64 t; cvta.to.shared.u64 t, %1; cvt.u32.u64 %0, t; }"
        : "=r"(a) : "l"(p));
    return a;
}
__device__ __forceinline__ uint32_t pack2(__nv_bfloat16 a, __nv_bfloat16 b) {
    return ((uint32_t)__bfloat16_as_ushort(b) << 16) | __bfloat16_as_ushort(a);
}

#define LDSM4(r0, r1, r2, r3, addr)                                            \
    asm volatile("ldmatrix.sync.aligned.m8n8.x4.shared.b16 {%0,%1,%2,%3}, [%4];" \
                 : "=r"(r0), "=r"(r1), "=r"(r2), "=r"(r3) : "r"(addr))

#define MMA_BF16(d, a, b)                                                      \
    asm volatile("mma.sync.aligned.m16n8k16.row.col.f32.bf16.bf16.f32 "        \
                 "{%0,%1,%2,%3}, {%4,%5,%6,%7}, {%8,%9}, {%0,%1,%2,%3};"       \
                 : "+f"((d)[0]), "+f"((d)[1]), "+f"((d)[2]), "+f"((d)[3])      \
                 : "r"((a)[0]), "r"((a)[1]), "r"((a)[2]), "r"((a)[3]),         \
                   "r"((b)[0]), "r"((b)[1]))

// ---------------------------------------------------------------------------
__global__ void build_rowidx_kernel() {
    int m = blockIdx.x * 256 + threadIdx.x;
    if (m >= MROWS) return;
    int win = m / NTOK, n = m % NTOK;
    int b  = win >> 6, wi = win & 63;
    int r = (wi >> 3) * WS + n / WS;
    int c = (wi & 7) * WS + n % WS;
    int sh = r + SS; if (sh >= IMG) sh -= IMG;
    int sw = c + SS; if (sw >= IMG) sw -= IMG;
    g_rowidx[m] = (b * IMG + sh) * IMG + sw;
}

__global__ void convert_w_kernel(const float* __restrict__ qkv_w,
                                 const float* __restrict__ proj_w) {
    int i = blockIdx.x * 256 + threadIdx.x;
    if (i < QKVC * CCH) {
        float v = qkv_w[i];
        __nv_bfloat16 h = __float2bfloat16(v);
        g_wqkv_hi[i] = h;
        g_wqkv_lo[i] = __float2bfloat16(v - __bfloat162float(h));
    }
    if (i < CCH * CCH) {
        float v = proj_w[i];
        __nv_bfloat16 h = __float2bfloat16(v);
        g_wp_hi[i] = h;
        g_wp_lo[i] = __float2bfloat16(v - __bfloat162float(h));
    }
}

// ---------------------------------------------------------------------------
// mma.sync GEMM: C[M,N] = A[M,512] @ W[N,512]^T + bias, bf16 3-term split.
// BM=BN=128, BK=32, 256 thr (8 warps 4x2, warp tile 32x64), double-buffered.
// SMEM buffer (32KB): Ahi/Alo/Bhi/Blo, each 128 rows x 64B, chunk-swizzled:
//   phys_chunk = c ^ ((r>>1)&3) ^ ((r>>3)&1)   (conflict-free ldmatrix+stores)
// ---------------------------------------------------------------------------
#define AHI 0
#define ALO 8192
#define BHI 16384
#define BLO 24576
#define BUFB 32768
#define NKCH 16            // 512/32

__device__ __forceinline__ uint32_t swz(int r, int c) {
    return (uint32_t)(r * 64 + ((c ^ ((r >> 1) & 3) ^ ((r >> 3) & 1)) << 4));
}

template <bool QKV>
__global__ __launch_bounds__(256)
void gemm_mma_kernel(const float* __restrict__ Ain,
                     const float* __restrict__ bias,
                     float* __restrict__ out)
{
    extern __shared__ char smem[];
    const uint32_t sbase = smem_u32(smem);
    const int tid = threadIdx.x;
    const int lane = tid & 31, warp = tid >> 5;
    const int wm = warp >> 1, wn = warp & 1;
    const int bm = blockIdx.y * 128, bn = blockIdx.x * 128;

    const float* __restrict__ A = QKV ? Ain : (const float*)g_att;
    const __nv_bfloat16* __restrict__ Whi = QKV ? g_wqkv_hi : g_wp_hi;
    const __nv_bfloat16* __restrict__ Wlo = QKV ? g_wqkv_lo : g_wp_lo;

    // ---- loader mapping: thread t -> row t/2, k-half t&1 (16 elems) ----
    const int lrow = tid >> 1, half = tid & 1;
    const size_t arow = QKV ? (size_t)g_rowidx[bm + lrow] * CCH
                            : (size_t)(bm + lrow) * CCH;
    const float* aptr = A + arow + half * 16;
    const __nv_bfloat16* bhptr = Whi + (size_t)(bn + lrow) * CCH + half * 16;
    const __nv_bfloat16* blptr = Wlo + (size_t)(bn + lrow) * CCH + half * 16;
    const uint32_t st0 = swz(lrow, 2 * half);
    const uint32_t st1 = swz(lrow, 2 * half + 1);

    // ---- per-lane ldmatrix offsets (buffer-relative) ----
    uint32_t aoff[2][2], boff[2][4];
#pragma unroll
    for (int s = 0; s < 2; s++) {
#pragma unroll
        for (int mt = 0; mt < 2; mt++) {
            int r = wm * 32 + mt * 16 + (lane & 15);
            aoff[s][mt] = swz(r, 2 * s + (lane >> 4));
        }
#pragma unroll
        for (int p = 0; p < 4; p++) {
            int n = wn * 64 + p * 16 + ((lane >> 4) & 1) * 8 + (lane & 7);
            boff[s][p] = swz(n, 2 * s + ((lane >> 3) & 1));
        }
    }

    float acc[2][8][4];
#pragma unroll
    for (int mt = 0; mt < 2; mt++)
#pragma unroll
        for (int nt = 0; nt < 8; nt++)
#pragma unroll
            for (int j = 0; j < 4; j++) acc[mt][nt][j] = 0.f;

    auto load_g = [&](int kt, float4* av, uint4* bhv, uint4* blv) {
#pragma unroll
        for (int i = 0; i < 4; i++)
            av[i] = *(const float4*)(aptr + kt * 32 + i * 4);
        bhv[0] = *(const uint4*)(bhptr + kt * 32);
        bhv[1] = *(const uint4*)(bhptr + kt * 32 + 8);
        blv[0] = *(const uint4*)(blptr + kt * 32);
        blv[1] = *(const uint4*)(blptr + kt * 32 + 8);
    };

    auto store_s = [&](int buf, const float4* av, const uint4* bhv,
                       const uint4* blv) {
        char* base = smem + buf * BUFB;
        uint32_t h[8], l[8];
#pragma unroll
        for (int i = 0; i < 4; i++) {
            __nv_bfloat16 h0 = __float2bfloat16(av[i].x);
            __nv_bfloat16 h1 = __float2bfloat16(av[i].y);
            __nv_bfloat16 h2 = __float2bfloat16(av[i].z);
            __nv_bfloat16 h3 = __float2bfloat16(av[i].w);
            h[2 * i]     = pack2(h0, h1);
            h[2 * i + 1] = pack2(h2, h3);
            l[2 * i] = pack2(__float2bfloat16(av[i].x - __bfloat162float(h0)),
                             __float2bfloat16(av[i].y - __bfloat162float(h1)));
            l[2 * i + 1] = pack2(__float2bfloat16(av[i].z - __bfloat162float(h2)),
                                 __float2bfloat16(av[i].w - __bfloat162float(h3)));
        }
        *(uint4*)(base + AHI + st0) = make_uint4(h[0], h[1], h[2], h[3]);
        *(uint4*)(base + AHI + st1) = make_uint4(h[4], h[5], h[6], h[7]);
        *(uint4*)(base + ALO + st0) = make_uint4(l[0], l[1], l[2], l[3]);
        *(uint4*)(base + ALO + st1) = make_uint4(l[4], l[5], l[6], l[7]);
        *(uint4*)(base + BHI + st0) = bhv[0];
        *(uint4*)(base + BHI + st1) = bhv[1];
        *(uint4*)(base + BLO + st0) = blv[0];
        *(uint4*)(base + BLO + st1) = blv[1];
    };

    auto compute = [&](uint32_t bb) {
#pragma unroll
        for (int s = 0; s < 2; s++) {
            uint32_t ah[2][4], al_[2][4];
#pragma unroll
            for (int mt = 0; mt < 2; mt++) {
                LDSM4(ah[mt][0], ah[mt][1], ah[mt][2], ah[mt][3],
                      bb + AHI + aoff[s][mt]);
                LDSM4(al_[mt][0], al_[mt][1], al_[mt][2], al_[mt][3],
                      bb + ALO + aoff[s][mt]);
            }
            uint32_t bh_[8][2], bl_[8][2];
#pragma unroll
            for (int p = 0; p < 4; p++) {
                uint32_t t0, t1, t2, t3;
                LDSM4(t0, t1, t2, t3, bb + BHI + boff[s][p]);
                bh_[2 * p][0] = t0; bh_[2 * p][1] = t1;
                bh_[2 * p + 1][0] = t2; bh_[2 * p + 1][1] = t3;
                LDSM4(t0, t1, t2, t3, bb + BLO + boff[s][p]);
                bl_[2 * p][0] = t0; bl_[2 * p][1] = t1;
                bl_[2 * p + 1][0] = t2; bl_[2 * p + 1][1] = t3;
            }
#pragma unroll
            for (int mt = 0; mt < 2; mt++)
#pragma unroll
                for (int nt = 0; nt < 8; nt++) {
                    MMA_BF16(acc[mt][nt], ah[mt], bh_[nt]);
                    MMA_BF16(acc[mt][nt], ah[mt], bl_[nt]);
                    MMA_BF16(acc[mt][nt], al_[mt], bh_[nt]);
                }
        }
    };

    // ---- prologue ----
    {
        float4 av[4]; uint4 bhv[2], blv[2];
        load_g(0, av, bhv, blv);
        store_s(0, av, bhv, blv);
    }
    __syncthreads();

    // ---- mainloop: prefetch k+1 to regs, compute k, store k+1, sync ----
    for (int kt = 0; kt < NKCH; kt++) {
        int cur = kt & 1;
        float4 av[4]; uint4 bhv[2], blv[2];
        if (kt + 1 < NKCH) load_g(kt + 1, av, bhv, blv);
        compute(sbase + cur * BUFB);
        if (kt + 1 < NKCH) store_s(cur ^ 1, av, bhv, blv);
        __syncthreads();
    }

    // ---- epilogue: fragment -> global fp32 with bias ----
#pragma unroll
    for (int mt = 0; mt < 2; mt++) {
        int mr = bm + wm * 32 + mt * 16 + (lane >> 2);
        size_t r0, r1;
        if (QKV) { r0 = (size_t)mr * QKVC; r1 = (size_t)(mr + 8) * QKVC; }
        else     { r0 = (size_t)g_rowidx[mr] * CCH;
                   r1 = (size_t)g_rowidx[mr + 8] * CCH; }
        float* bp = QKV ? g_qkv : out;
        const int cbase = bn + wn * 64 + 2 * (lane & 3);
        float* p0 = bp + r0 + cbase;
        float* p1 = bp + r1 + cbase;
#pragma unroll
        for (int nt = 0; nt < 8; nt++) {
            float2 bb = *(const float2*)(bias + cbase + nt * 8);
            float2 v0, v1;
            v0.x = acc[mt][nt][0] + bb.x; v0.y = acc[mt][nt][1] + bb.y;
            v1.x = acc[mt][nt][2] + bb.x; v1.y = acc[mt][nt][3] + bb.y;
            *(float2*)(p0 + nt * 8) = v0;
            *(float2*)(p1 + nt * 8) = v1;
        }
    }
}

// ---------------------------------------------------------------------------
// Attention: one block per (window, head). 256 threads. (unchanged)
// ---------------------------------------------------------------------------
#define QKS 33

__global__ __launch_bounds__(256)
void attn_kernel(const float* __restrict__ rel)
{
    const int win = blockIdx.x >> 4;
    const int h   = blockIdx.x & 15;
    const int tid = threadIdx.x;

    __shared__ float qs[NTOK * QKS];
    __shared__ float ks[NTOK * QKS];
    __shared__ float vs[NTOK * QKS];
    __shared__ float S[NTOK][50];
    __shared__ float tb[169];
    __shared__ int   lab[NTOK];

    const float scale = 0.17677669529663687f;
    const size_t base = (size_t)win * NTOK * QKVC + h * HD;

    for (int e = tid; e < NTOK * 8; e += 256) {
        int n = e >> 3, c4 = (e & 7) * 4;
        const float* p = g_qkv + base + (size_t)n * QKVC + c4;
        float4 q4 = *(const float4*)(p);
        float4 k4 = *(const float4*)(p + 512);
        float4 v4 = *(const float4*)(p + 1024);
        float* qd = &qs[n * QKS + c4];
        float* kd = &ks[n * QKS + c4];
        float* vd = &vs[n * QKS + c4];
        qd[0] = q4.x * scale; qd[1] = q4.y * scale;
        qd[2] = q4.z * scale; qd[3] = q4.w * scale;
        kd[0] = k4.x; kd[1] = k4.y; kd[2] = k4.z; kd[3] = k4.w;
        vd[0] = v4.x; vd[1] = v4.y; vd[2] = v4.z; vd[3] = v4.w;
    }
    if (tid < 169) tb[tid] = rel[tid * NHEAD + h];
    if (tid < NTOK) {
        int wi = win & 63;
        int r = (wi >> 3) * WS + tid / WS;
        int c = (wi & 7) * WS + tid % WS;
        int rh = (r < IMG - WS) ? 0 : (r < IMG - SS ? 1 : 2);
        int rw = (c < IMG - WS) ? 0 : (c < IMG - SS ? 1 : 2);
        lab[tid] = rh * 3 + rw;
    }
    __syncthreads();

    for (int e = tid; e < NTOK * NTOK; e += 256) {
        int n = e / NTOK, mm = e - n * NTOK;
        const float* qp = &qs[n * QKS];
        const float* kp = &ks[mm * QKS];
        float a = 0.f;
#pragma unroll
        for (int d = 0; d < HD; d++) a = fmaf(qp[d], kp[d], a);
        int dr = n / WS - mm / WS + (WS - 1);
        int dc = n % WS - mm % WS + (WS - 1);
        a += tb[dr * (2 * WS - 1) + dc];
        if (lab[n] != lab[mm]) a -= 100.0f;
        S[n][mm] = a;
    }
    __syncthreads();

    const int warp = tid >> 5, lane = tid & 31;
    for (int n = warp; n < NTOK; n += 8) {
        float v0 = (lane < NTOK)      ? S[n][lane]      : -1e30f;
        float v1 = (lane + 32 < NTOK) ? S[n][lane + 32] : -1e30f;
        float mx = fmaxf(v0, v1);
#pragma unroll
        for (int o = 16; o > 0; o >>= 1)
            mx = fmaxf(mx, __shfl_xor_sync(0xffffffffu, mx, o));
        float e0 = (lane < NTOK)      ? __expf(v0 - mx) : 0.f;
        float e1 = (lane + 32 < NTOK) ? __expf(v1 - mx) : 0.f;
        float sm = e0 + e1;
#pragma unroll
        for (int o = 16; o > 0; o >>= 1)
            sm += __shfl_xor_sync(0xffffffffu, sm, o);
        float inv = 1.0f / sm;
        if (lane < NTOK)      S[n][lane]      = e0 * inv;
        if (lane + 32 < NTOK) S[n][lane + 32] = e1 * inv;
    }
    __syncthreads();

    const size_t obase = (size_t)win * NTOK * CCH + h * HD;
    for (int e = tid; e < NTOK * HD; e += 256) {
        int n = e >> 5, d = e & 31;
        float a = 0.f;
#pragma unroll
        for (int mm = 0; mm < NTOK; mm++)
            a = fmaf(S[n][mm], vs[mm * QKS + d], a);
        g_att[obase + (size_t)n * CCH + d] = a;
    }
}

// ---------------------------------------------------------------------------
extern "C" void kernel_launch(void* const* d_in, const int* in_sizes, int n_in,
                              void* d_out, int out_size)
{
    const float* x      = (const float*)d_in[0];
    const float* qkv_w  = (const float*)d_in[1];
    const float* qkv_b  = (const float*)d_in[2];
    const float* proj_w = (const float*)d_in[3];
    const float* proj_b = (const float*)d_in[4];
    const float* rel    = (const float*)d_in[5];
    float* out = (float*)d_out;

    cudaFuncSetAttribute(gemm_mma_kernel<true>,
                         cudaFuncAttributeMaxDynamicSharedMemorySize, 2 * BUFB);
    cudaFuncSetAttribute(gemm_mma_kernel<false>,
                         cudaFuncAttributeMaxDynamicSharedMemorySize, 2 * BUFB);

    build_rowidx_kernel<<<(MROWS + 255) / 256, 256>>>();
    convert_w_kernel<<<(QKVC * CCH + 255) / 256, 256>>>(qkv_w, proj_w);

    // QKV: M=100352, N=1536 (gather-A from x)
    gemm_mma_kernel<true><<<dim3(QKVC / 128, MROWS / 128), 256, 2 * BUFB>>>(
        x, qkv_b, nullptr);

    attn_kernel<<<TOTWIN * NHEAD, 256>>>(rel);

    // proj: M=100352, N=512 (A = g_att in-kernel, scatter-C to out)
    gemm_mma_kernel<false><<<dim3(CCH / 128, MROWS / 128), 256, 2 * BUFB>>>(
        nullptr, proj_b, out);
}